// round 9
// baseline (speedup 1.0000x reference)
#include <cuda_runtime.h>
#include <cuda_bf16.h>
#include <math.h>
#include <stdint.h>

#define NN 2048
#define DD 64
#define PP 32
#define NSTOP 512
#define KIN 4131          // 2*N + 3 + P
#define KPAD 4160         // 130 chunks of 32
#define NCHUNK 130
#define BM 256
#define BN 128
#define NSTG 4
#define TILE_U32 2048     // 128x32 bf16 tile = 2048 uint32 = 8KB
#define STAGE_U32 6144    // A0 + A1 + B
#define STAGE_B 24576
#define GEMM_SMEM (NSTG * STAGE_B)

// ---------------- scratch (device globals: allocation-free) ----------------
__device__ unsigned d_kmask[NN / 32];
__device__ int   d_klist[NSTOP];
__device__ int   d_nk;
__device__ __align__(16) float d_xn[NN * DD];
__device__ __align__(16) float d_xnc[NSTOP * DD];
__device__ __align__(16) float d_xnct[DD * NSTOP];   // transposed kept rows
__device__ __align__(16) float d_embc[NSTOP * DD];
__device__ __align__(16) float d_aggn[NN * DD];
__device__ unsigned d_adjm[NSTOP * 16];              // adjacency bitmask [b][16 words]
__device__ float d_pref[NN * PP];
__device__ float d_av[NN];
__device__ float d_bv[NN];
// m16n8k16 bf16 fragment-packed operands
__device__ __align__(128) uint32_t d_apack[(size_t)NN * KPAD / 2];
__device__ __align__(128) uint32_t d_bpack[(size_t)NN * KPAD / 2];

// ---------------- helpers ----------------
__device__ __forceinline__ uint32_t smem_u32(const void* p) {
    uint32_t a;
    asm("{ .reg .u64 t; cvta.to.shared.u64 t, %1; cvt.u32.u64 %0, t; }" : "=r"(a) : "l"(p));
    return a;
}
__device__ __forceinline__ uint32_t pack_bf16(float a, float b) {
    __nv_bfloat162 h = __floats2bfloat162_rn(a, b);
    return *(uint32_t*)&h;
}
#define CP_ASYNC16(dst, src) \
    asm volatile("cp.async.cg.shared.global [%0], [%1], 16;" :: "r"(dst), "l"(src) : "memory")
#define CP_COMMIT() asm volatile("cp.async.commit_group;" ::: "memory")
#define CP_WAIT(n)  asm volatile("cp.async.wait_group %0;" :: "n"(n) : "memory")

#define MMA16(c, a, b) \
    asm volatile("mma.sync.aligned.m16n8k16.row.col.f32.bf16.bf16.f32 " \
        "{%0,%1,%2,%3},{%4,%5,%6,%7},{%8,%9},{%0,%1,%2,%3};" \
        : "+f"((c)[0]), "+f"((c)[1]), "+f"((c)[2]), "+f"((c)[3]) \
        : "r"((a)[0]), "r"((a)[1]), "r"((a)[2]), "r"((a)[3]), \
          "r"((b)[0]), "r"((b)[1]))

__device__ __forceinline__ int keep_bit(int i) {
    return (d_kmask[i >> 5] >> (i & 31)) & 1;
}

// ---------------- init: zero + row-normalize ----------------
__global__ void k_init(const float* __restrict__ emb) {      // grid NN, block 64
    int i = blockIdx.x;
    int t = threadIdx.x;
    int idx = i * DD + t;
    d_aggn[idx] = 0.f;
    if (idx < NSTOP * 16) d_adjm[idx] = 0u;
    if (idx < NN / 32) d_kmask[idx] = 0u;
    if (idx == 0) d_nk = 0;

    float v = emb[idx];
    float s = v * v;
    #pragma unroll
    for (int o = 16; o; o >>= 1) s += __shfl_down_sync(0xffffffffu, s, o);
    __shared__ float ws[2];
    if ((t & 31) == 0) ws[t >> 5] = s;
    __syncthreads();
    float norm = fmaxf(sqrtf(ws[0] + ws[1]), 1e-8f);
    d_xn[idx] = v / norm;
}
__global__ void k_scatter(const int* __restrict__ stops) {
    int i = blockIdx.x * blockDim.x + threadIdx.x;
    if (i < NSTOP) {
        int s = stops[i];
        atomicOr(&d_kmask[s >> 5], 1u << (s & 31));
    }
}

// ---------------- deterministic compaction of kept rows (+ transpose) ----------
__global__ void k_compact(const float* __restrict__ emb) {   // grid NN, block 64
    int i = blockIdx.x, t = threadIdx.x;
    unsigned w = d_kmask[i >> 5];
    if (!((w >> (i & 31)) & 1)) return;
    __shared__ int spos;
    if (t == 0) {
        int pos = 0;
        for (int q = 0; q < (i >> 5); q++) pos += __popc(d_kmask[q]);
        pos += __popc(w & ((1u << (i & 31)) - 1u));
        spos = pos;
        d_klist[pos] = i;
        atomicMax(&d_nk, pos + 1);
    }
    __syncthreads();
    int pos = spos;
    float xv = d_xn[i * DD + t];
    d_xnc[pos * DD + t] = xv;
    d_xnct[t * NSTOP + pos] = xv;
    d_embc[pos * DD + t] = emb[i * DD + t];
}

// ---------------- sim tiles 16b x 128j -> adjacency bitmask ----------------
__global__ void k_sim() {                                    // grid (32,4), block 128
    int bx = blockIdx.x, y = blockIdx.y, t = threadIdx.x;
    int nk = d_nk;
    int b0 = bx * 16;
    if (b0 >= nk) return;
    __shared__ __align__(16) float xi[DD * 16];              // [d][16]
    #pragma unroll
    for (int q = 0; q < 8; q++) {
        int idx = q * 128 + t;                               // (bb, d) row-major read
        int bb = idx >> 6, d = idx & 63;
        xi[d * 16 + bb] = d_xnc[(b0 + bb) * DD + d];
    }
    __syncthreads();

    int lane = t & 31, wid = t >> 5;
    int j = y * 128 + t;
    float acc[16];
    #pragma unroll
    for (int bb = 0; bb < 16; bb++) acc[bb] = 0.f;

    const float4* xi4 = (const float4*)xi;
    #pragma unroll 8
    for (int d = 0; d < DD; d++) {
        float xv = d_xnct[d * NSTOP + j];                    // coalesced; 0 for j>=nk
        float4 c0 = xi4[d * 4 + 0], c1 = xi4[d * 4 + 1];
        float4 c2 = xi4[d * 4 + 2], c3 = xi4[d * 4 + 3];
        acc[0]  = fmaf(xv, c0.x, acc[0]);  acc[1]  = fmaf(xv, c0.y, acc[1]);
        acc[2]  = fmaf(xv, c0.z, acc[2]);  acc[3]  = fmaf(xv, c0.w, acc[3]);
        acc[4]  = fmaf(xv, c1.x, acc[4]);  acc[5]  = fmaf(xv, c1.y, acc[5]);
        acc[6]  = fmaf(xv, c1.z, acc[6]);  acc[7]  = fmaf(xv, c1.w, acc[7]);
        acc[8]  = fmaf(xv, c2.x, acc[8]);  acc[9]  = fmaf(xv, c2.y, acc[9]);
        acc[10] = fmaf(xv, c2.z, acc[10]); acc[11] = fmaf(xv, c2.w, acc[11]);
        acc[12] = fmaf(xv, c3.x, acc[12]); acc[13] = fmaf(xv, c3.y, acc[13]);
        acc[14] = fmaf(xv, c3.z, acc[14]); acc[15] = fmaf(xv, c3.w, acc[15]);
    }

    #pragma unroll
    for (int bb = 0; bb < 16; bb++) {
        int b = b0 + bb;
        bool pred = (j < nk) && (b < nk) && (j != b) && (acc[bb] > 0.5f);
        unsigned m = __ballot_sync(0xffffffffu, pred);
        if (lane == 0 && b < nk) d_adjm[b * 16 + y * 4 + wid] = m;
    }
}

// ---------------- masked aggregation + divide ----------------
__global__ void k_aggm() {                                   // grid NSTOP, block 128
    int b = blockIdx.x, t = threadIdx.x;
    if (b >= d_nk) return;
    __shared__ unsigned mw[16];
    __shared__ float aggp[128];
    if (t < 16) mw[t] = d_adjm[b * 16 + t];
    __syncthreads();
    int deg = 0;
    #pragma unroll
    for (int w = 0; w < 16; w++) deg += __popc(mw[w]);

    int d = t & 63, half = t >> 6;
    float p = 0.f;
    #pragma unroll
    for (int w = half * 8; w < half * 8 + 8; w++) {
        unsigned mm = mw[w];
        while (mm) {
            int bit = __ffs(mm) - 1;
            mm &= mm - 1;
            p += d_embc[(w * 32 + bit) * DD + d];
        }
    }
    aggp[t] = p;
    __syncthreads();
    if (t < DD) {
        float s = aggp[t] + aggp[t + 64];
        d_aggn[d_klist[b] * DD + t] = s / fmaxf((float)deg, 1.0f);
    }
}

// ---------------- pref + edge vectors (8 rows/block) ----------------
__global__ void k_pref(const float* __restrict__ emb,
                       const float* __restrict__ llw, const float* __restrict__ llb,
                       const float* __restrict__ lrw, const float* __restrict__ ew) {
    int i = blockIdx.x * 8 + (threadIdx.x >> 5);
    int p = threadIdx.x & 31;
    float s = llb[p];
    const float* ai = d_aggn + i * DD;
    const float* ei = emb + i * DD;
    #pragma unroll
    for (int d = 0; d < DD; d++)
        s += ai[d] * llw[p * DD + d] + ei[d] * lrw[p * DD + d];
    d_pref[i * PP + p] = s;
    float a = s * ew[p];
    float b = s * ew[PP + p];
    #pragma unroll
    for (int o = 16; o; o >>= 1) {
        a += __shfl_down_sync(0xffffffffu, a, o);
        b += __shfl_down_sync(0xffffffffu, b, o);
    }
    if (p == 0) { d_av[i] = a; d_bv[i] = b; }
}

// ---------------- combined value at (i,k) ----------------
__device__ __forceinline__ float comb_val(int i, int k, const float* __restrict__ dist,
                                          float eb, float wkf, float vhf) {
    if (k < PP) return d_pref[i * PP + k];
    if (k < PP + NN) {
        float e = d_av[i] + d_bv[k - PP] + eb;
        return (e >= 0.f) ? e : 0.01f * e;
    }
    if (k < PP + 2 * NN) return dist[(size_t)i * NN + (k - PP - NN)];
    if (k == PP + 2 * NN) return wkf;
    if (k == PP + 2 * NN + 1) return vhf;
    if (k == PP + 2 * NN + 2) return keep_bit(i) ? 1.f : 0.f;
    return 0.f;
}

// ---------------- A fill: fragment-offset iteration, coalesced uint4 stores ----
__global__ void k_fill_a(const float* __restrict__ dist, const float* __restrict__ edge_b,
                         const int* __restrict__ wk, const int* __restrict__ vh) {
    int kc = blockIdx.x, mt = blockIdx.y;
    int t = threadIdx.x;                 // 512
    int lane = t & 31, fragq = t >> 5;   // fragq 0..15
    int ki = fragq >> 3, mi = fragq & 7;
    int g = lane >> 2, tg = lane & 3;
    int i0 = mt * 128 + mi * 16 + g;
    int i1 = i0 + 8;
    int kA = kc * 32 + ki * 16 + tg * 2;
    int kB = kA + 8;
    float eb = edge_b[0], wkf = (float)wk[0], vhf = (float)vh[0];
    uint4 v;
    v.x = pack_bf16(comb_val(i0, kA, dist, eb, wkf, vhf), comb_val(i0, kA + 1, dist, eb, wkf, vhf));
    v.y = pack_bf16(comb_val(i1, kA, dist, eb, wkf, vhf), comb_val(i1, kA + 1, dist, eb, wkf, vhf));
    v.z = pack_bf16(comb_val(i0, kB, dist, eb, wkf, vhf), comb_val(i0, kB + 1, dist, eb, wkf, vhf));
    v.w = pack_bf16(comb_val(i1, kB, dist, eb, wkf, vhf), comb_val(i1, kB + 1, dist, eb, wkf, vhf));
    *(uint4*)(d_apack + (size_t)(mt * NCHUNK + kc) * TILE_U32 + fragq * 128 + lane * 4) = v;
}

// ---------------- B fill: fragment-offset iteration, coalesced uint2 stores ----
__global__ void k_fill_b(const float* __restrict__ combw) {
    int kc = blockIdx.x, nt = blockIdx.y;
    int t = threadIdx.x;                 // 1024
    int lane = t & 31, fragq = t >> 5;   // fragq 0..31
    int ki = fragq >> 4, ni = fragq & 15;
    int gb = lane >> 2, tg = lane & 3;
    int i = nt * 128 + ni * 8 + gb;      // weight row = output column
    int k0 = kc * 32 + ki * 16 + tg * 2;
    int k1 = k0 + 8;
    const float* wrow = combw + (size_t)i * KIN;
    float a0 = (k0     < KIN) ? wrow[k0]     : 0.f;
    float a1 = (k0 + 1 < KIN) ? wrow[k0 + 1] : 0.f;
    float b0 = (k1     < KIN) ? wrow[k1]     : 0.f;
    float b1 = (k1 + 1 < KIN) ? wrow[k1 + 1] : 0.f;
    uint2 v;
    v.x = pack_bf16(a0, a1);
    v.y = pack_bf16(b0, b1);
    *(uint2*)(d_bpack + (size_t)(nt * NCHUNK + kc) * TILE_U32 + fragq * 64 + lane * 2) = v;
}

// ---------------- stage loader: 24KB (A0,A1,B), 256 threads ----------------
__device__ __forceinline__ void load_stage(uint32_t sbase, int s,
                                           const uint32_t* a0, const uint32_t* a1,
                                           const uint32_t* bP, int tid) {
    uint32_t dst = sbase + s * STAGE_B + tid * 16;
    CP_ASYNC16(dst,          a0 + tid * 4);
    CP_ASYNC16(dst + 4096,   a0 + 1024 + tid * 4);
    CP_ASYNC16(dst + 8192,   a1 + tid * 4);
    CP_ASYNC16(dst + 12288,  a1 + 1024 + tid * 4);
    CP_ASYNC16(dst + 16384,  bP + tid * 4);
    CP_ASYNC16(dst + 20480,  bP + 1024 + tid * 4);
}

// ---------------- bf16 mma GEMM: C[256x128] per CTA, 8 warps 64x64 each --------
__global__ __launch_bounds__(256, 1) void k_gemm_mma(const float* __restrict__ bias,
                                                     float* __restrict__ C) {
    extern __shared__ __align__(16) uint32_t smu[];
    int tid = threadIdx.x, lane = tid & 31, wid = tid >> 5;
    int warpM = wid & 3, warpN = wid >> 2;      // 4 x 2 warps, each 64x64
    int mt = blockIdx.y, nt = blockIdx.x;
    const uint32_t* a0 = d_apack + (size_t)(mt * 2)     * NCHUNK * TILE_U32;
    const uint32_t* a1 = d_apack + (size_t)(mt * 2 + 1) * NCHUNK * TILE_U32;
    const uint32_t* bP = d_bpack + (size_t)nt * NCHUNK * TILE_U32;
    uint32_t sbase = smem_u32(smu);

    float acc[4][8][4];
    #pragma unroll
    for (int m = 0; m < 4; m++)
        #pragma unroll
        for (int n = 0; n < 8; n++)
            #pragma unroll
            for (int q = 0; q < 4; q++) acc[m][n][q] = 0.f;

    #pragma unroll
    for (int p = 0; p < NSTG - 1; p++) {
        load_stage(sbase, p, a0 + (size_t)p * TILE_U32, a1 + (size_t)p * TILE_U32,
                   bP + (size_t)p * TILE_U32, tid);
        CP_COMMIT();
    }

    for (int kc = 0; kc < NCHUNK; kc++) {
        CP_WAIT(NSTG - 2);
        __syncthreads();
        int pf = kc + NSTG - 1;
        if (pf < NCHUNK)
            load_stage(sbase, pf % NSTG, a0 + (size_t)pf * TILE_U32,
                       a1 + (size_t)pf * TILE_U32, bP + (size_t)pf * TILE_U32, tid);
        CP_COMMIT();

        const uint32_t* As = smu + (kc % NSTG) * STAGE_U32;
        const uint32_t* Bs = As + 4096;
        #pragma unroll
        for (int ki = 0; ki < 2; ki++) {
            uint32_t af[4][4];
            #pragma unroll
            for (int m = 0; m < 4; m++) {
                int fr = warpM * 4 + m;                      // 0..15 across two A tiles
                const uint32_t* base = As + (fr >> 3) * 2048;
                uint4 v = *(const uint4*)(base + ((ki * 8 + (fr & 7)) * 128 + lane * 4));
                af[m][0] = v.x; af[m][1] = v.y; af[m][2] = v.z; af[m][3] = v.w;
            }
            uint32_t bf[8][2];
            #pragma unroll
            for (int n = 0; n < 8; n++) {
                uint2 w = *(const uint2*)(Bs + ((ki * 16 + warpN * 8 + n) * 64 + lane * 2));
                bf[n][0] = w.x; bf[n][1] = w.y;
            }
            #pragma unroll
            for (int m = 0; m < 4; m++)
                #pragma unroll
                for (int n = 0; n < 8; n++) MMA16(acc[m][n], af[m], bf[n]);
        }
    }

    // epilogue
    int g = lane >> 2, tg = lane & 3;
    int rowBase = mt * BM + warpM * 64;
    int colBase = nt * BN + warpN * 64;
    #pragma unroll
    for (int m = 0; m < 4; m++) {
        int r0 = rowBase + m * 16 + g;
        #pragma unroll
        for (int n = 0; n < 8; n++) {
            int c = colBase + n * 8 + tg * 2;
            float2 bb = *(const float2*)(bias + c);
            float2 o0 = { acc[m][n][0] + bb.x, acc[m][n][1] + bb.y };
            float2 o1 = { acc[m][n][2] + bb.x, acc[m][n][3] + bb.y };
            *(float2*)(C + (size_t)r0 * NN + c) = o0;
            *(float2*)(C + (size_t)(r0 + 8) * NN + c) = o1;
        }
    }
}

// ---------------- register-resident row log-softmax ----------------
__global__ void k_lsm(float* __restrict__ out) {
    int i = blockIdx.x;
    int t = threadIdx.x;                 // 256
    int lane = t & 31, wid = t >> 5;
    float4* rp = (float4*)(out + (size_t)i * NN);
    float4 v0 = rp[t];
    float4 v1 = rp[t + 256];

    float m = fmaxf(fmaxf(fmaxf(v0.x, v0.y), fmaxf(v0.z, v0.w)),
                    fmaxf(fmaxf(v1.x, v1.y), fmaxf(v1.z, v1.w)));
    #pragma unroll
    for (int o = 16; o; o >>= 1) m = fmaxf(m, __shfl_xor_sync(0xffffffffu, m, o));
    __shared__ float sA[8];
    __shared__ float sbc;
    if (lane == 0) sA[wid] = m;
    __syncthreads();
    if (t == 0) {
        float mm = sA[0];
        #pragma unroll
        for (int w = 1; w < 8; w++) mm = fmaxf(mm, sA[w]);
        sbc = mm;
    }
    __syncthreads();
    float mx = sbc;

    float s = __expf(v0.x - mx) + __expf(v0.y - mx) + __expf(v0.z - mx) + __expf(v0.w - mx)
            + __expf(v1.x - mx) + __expf(v1.y - mx) + __expf(v1.z - mx) + __expf(v1.w - mx);
    #pragma unroll
    for (int o = 16; o; o >>= 1) s += __shfl_xor_sync(0xffffffffu, s, o);
    __syncthreads();
    if (lane == 0) sA[wid] = s;
    __syncthreads();
    if (t == 0) {
        float ss = 0.f;
        #pragma unroll
        for (int w = 0; w < 8; w++) ss += sA[w];
        sbc = logf(ss) + mx;
    }
    __syncthreads();
    float lse = sbc;

    v0.x -= lse; v0.y -= lse; v0.z -= lse; v0.w -= lse;
    v1.x -= lse; v1.y -= lse; v1.z -= lse; v1.w -= lse;
    rp[t] = v0;
    rp[t + 256] = v1;
}

// ---------------- launch ----------------
extern "C" void kernel_launch(void* const* d_in, const int* in_sizes, int n_in,
                              void* d_out, int out_size) {
    const float* dist   = (const float*)d_in[0];
    const float* emb    = (const float*)d_in[1];
    const float* llw    = (const float*)d_in[2];
    const float* llb    = (const float*)d_in[3];
    const float* lrw    = (const float*)d_in[4];
    const float* ew     = (const float*)d_in[5];
    const float* edge_b = (const float*)d_in[6];
    const float* combw  = (const float*)d_in[7];
    const float* combb  = (const float*)d_in[8];
    const int*   stops  = (const int*)d_in[9];
    const int*   wk     = (const int*)d_in[10];
    const int*   vh     = (const int*)d_in[11];
    float* out = (float*)d_out;

    k_init<<<NN, DD>>>(emb);
    k_scatter<<<(NSTOP + 255) / 256, 256>>>(stops);
    k_compact<<<NN, DD>>>(emb);
    k_sim<<<dim3(32, 4), 128>>>();
    k_aggm<<<NSTOP, 128>>>();
    k_pref<<<NN / 8, 256>>>(emb, llw, llb, lrw, ew);

    dim3 fg(NCHUNK, 16);
    k_fill_a<<<fg, 512>>>(dist, edge_b, wk, vh);
    k_fill_b<<<fg, 1024>>>(combw);

    cudaFuncSetAttribute(k_gemm_mma, cudaFuncAttributeMaxDynamicSharedMemorySize, GEMM_SMEM);
    dim3 gg(NN / BN, NN / BM);
    k_gemm_mma<<<gg, 256, GEMM_SMEM>>>(combb, out);

    k_lsm<<<NN, 256>>>(out);
}

// round 10
// speedup vs baseline: 1.1686x; 1.1686x over previous
#include <cuda_runtime.h>
#include <cuda_bf16.h>
#include <math.h>
#include <stdint.h>

#define NN 2048
#define DD 64
#define PP 32
#define NSTOP 512
#define KIN 4131          // 2*N + 3 + P
#define KPAD 4160         // 130 chunks of 32
#define NCHUNK 130
#define BM 128
#define BN 128
#define NSTG 4
#define TILE_U32 2048     // 128x32 bf16 = 2048 uint32 = 8KB
#define STAGE_U32 4096
#define STAGE_B 16384
#define GEMM_SMEM (NSTG * STAGE_B)

// ---------------- scratch (device globals: allocation-free) ----------------
__device__ unsigned d_kmask[NN / 32];
__device__ int   d_klist[NSTOP];
__device__ int   d_nk;
__device__ __align__(16) float d_xn[NN * DD];
__device__ __align__(16) float d_xnc[NSTOP * DD];
__device__ __align__(16) float d_embc[NSTOP * DD];
__device__ __align__(16) float d_aggn[NN * DD];
__device__ float d_pref[NN * PP];
__device__ float d_av[NN];
__device__ float d_bv[NN];
// m16n8k16 bf16 fragment-packed operands
__device__ __align__(128) uint32_t d_apack[(size_t)NN * KPAD / 2];
__device__ __align__(128) uint32_t d_bpack[(size_t)NN * KPAD / 2];

// ---------------- helpers ----------------
__device__ __forceinline__ uint32_t smem_u32(const void* p) {
    uint32_t a;
    asm("{ .reg .u64 t; cvta.to.shared.u64 t, %1; cvt.u32.u64 %0, t; }" : "=r"(a) : "l"(p));
    return a;
}
__device__ __forceinline__ uint32_t pack_bf16(float a, float b) {
    __nv_bfloat162 h = __floats2bfloat162_rn(a, b);
    return *(uint32_t*)&h;
}
#define CP_ASYNC16(dst, src) \
    asm volatile("cp.async.cg.shared.global [%0], [%1], 16;" :: "r"(dst), "l"(src) : "memory")
#define CP_COMMIT() asm volatile("cp.async.commit_group;" ::: "memory")
#define CP_WAIT(n)  asm volatile("cp.async.wait_group %0;" :: "n"(n) : "memory")

#define MMA16(c, a, b) \
    asm volatile("mma.sync.aligned.m16n8k16.row.col.f32.bf16.bf16.f32 " \
        "{%0,%1,%2,%3},{%4,%5,%6,%7},{%8,%9},{%0,%1,%2,%3};" \
        : "+f"((c)[0]), "+f"((c)[1]), "+f"((c)[2]), "+f"((c)[3]) \
        : "r"((a)[0]), "r"((a)[1]), "r"((a)[2]), "r"((a)[3]), \
          "r"((b)[0]), "r"((b)[1]))

__device__ __forceinline__ int keep_bit(int i) {
    return (d_kmask[i >> 5] >> (i & 31)) & 1;
}

// ---------------- init: zero + row-normalize ----------------
__global__ void k_init(const float* __restrict__ emb) {      // grid NN, block 64
    int i = blockIdx.x;
    int t = threadIdx.x;
    int idx = i * DD + t;
    d_aggn[idx] = 0.f;
    if (idx < NN / 32) d_kmask[idx] = 0u;
    if (idx == 0) d_nk = 0;

    float v = emb[idx];
    float s = v * v;
    #pragma unroll
    for (int o = 16; o; o >>= 1) s += __shfl_down_sync(0xffffffffu, s, o);
    __shared__ float ws[2];
    if ((t & 31) == 0) ws[t >> 5] = s;
    __syncthreads();
    float norm = fmaxf(sqrtf(ws[0] + ws[1]), 1e-8f);
    d_xn[idx] = v / norm;
}
__global__ void k_scatter(const int* __restrict__ stops) {
    int i = blockIdx.x * blockDim.x + threadIdx.x;
    if (i < NSTOP) {
        int s = stops[i];
        atomicOr(&d_kmask[s >> 5], 1u << (s & 31));
    }
}

// ---------------- deterministic compaction of kept rows ----------------
__global__ void k_compact(const float* __restrict__ emb) {   // grid NN, block 64
    int i = blockIdx.x, t = threadIdx.x;
    unsigned w = d_kmask[i >> 5];
    if (!((w >> (i & 31)) & 1)) return;
    __shared__ int spos;
    if (t == 0) {
        int pos = 0;
        for (int q = 0; q < (i >> 5); q++) pos += __popc(d_kmask[q]);
        pos += __popc(w & ((1u << (i & 31)) - 1u));
        spos = pos;
        d_klist[pos] = i;
        atomicMax(&d_nk, pos + 1);
    }
    __syncthreads();
    int pos = spos;
    d_xnc[pos * DD + t] = d_xn[i * DD + t];
    d_embc[pos * DD + t] = emb[i * DD + t];
}

// ---------------- fused sim+agg: 4 lanes per j-row, high occupancy ----------
__global__ void k_aggv2() {                                  // grid NSTOP, block 256
    int b = blockIdx.x, t = threadIdx.x;
    int nk = d_nk;
    if (b >= nk) return;
    __shared__ __align__(16) float xi[DD];
    __shared__ unsigned mw[16];
    __shared__ float aggp[256];
    if (t < DD) xi[t] = d_xnc[b * DD + t];
    __syncthreads();

    int lane = t & 31, w = t >> 5;       // 8 warps; warp w owns j in [64w, 64w+64)
    int qt = lane & 3;                   // quarter of a row (16 floats)
    const float4* xq = (const float4*)(xi + qt * 16);
    float4 x0 = xq[0], x1 = xq[1], x2 = xq[2], x3 = xq[3];

    unsigned word = 0;
    #pragma unroll
    for (int sub = 0; sub < 8; sub++) {
        int j = w * 64 + sub * 8 + (lane >> 2);
        const float4* xj = (const float4*)(d_xnc + j * DD + qt * 16);
        float4 a0 = xj[0], a1 = xj[1], a2 = xj[2], a3 = xj[3];
        float s = a0.x * x0.x + a0.y * x0.y + a0.z * x0.z + a0.w * x0.w
                + a1.x * x1.x + a1.y * x1.y + a1.z * x1.z + a1.w * x1.w
                + a2.x * x2.x + a2.y * x2.y + a2.z * x2.z + a2.w * x2.w
                + a3.x * x3.x + a3.y * x3.y + a3.z * x3.z + a3.w * x3.w;
        s += __shfl_xor_sync(0xffffffffu, s, 1);
        s += __shfl_xor_sync(0xffffffffu, s, 2);
        bool pred = (qt == 0) && (j < nk) && (j != b) && (s > 0.5f);
        unsigned m = __ballot_sync(0xffffffffu, pred);       // bits at 4r
        unsigned b8 = 0;
        #pragma unroll
        for (int r = 0; r < 8; r++) b8 |= ((m >> (4 * r)) & 1u) << r;
        word |= b8 << ((sub & 3) * 8);
        if ((sub & 3) == 3) {
            if (lane == 0) mw[w * 2 + (sub >> 2)] = word;
            word = 0;
        }
    }
    __syncthreads();

    int deg = 0;
    #pragma unroll
    for (int q = 0; q < 16; q++) deg += __popc(mw[q]);

    int d = t & 63, part = t >> 6;       // 4 parts x 4 words each
    float p = 0.f;
    #pragma unroll
    for (int q = part * 4; q < part * 4 + 4; q++) {
        unsigned mm = mw[q];
        while (mm) {
            int bit = __ffs(mm) - 1;
            mm &= mm - 1;
            p += d_embc[(q * 32 + bit) * DD + d];
        }
    }
    aggp[t] = p;
    __syncthreads();
    if (t < DD) {
        float s = aggp[t] + aggp[t + 64] + aggp[t + 128] + aggp[t + 192];
        d_aggn[d_klist[b] * DD + t] = s / fmaxf((float)deg, 1.0f);
    }
}

// ---------------- pref + edge vectors (8 rows/block) ----------------
__global__ void k_pref(const float* __restrict__ emb,
                       const float* __restrict__ llw, const float* __restrict__ llb,
                       const float* __restrict__ lrw, const float* __restrict__ ew) {
    int i = blockIdx.x * 8 + (threadIdx.x >> 5);
    int p = threadIdx.x & 31;
    float s = llb[p];
    const float* ai = d_aggn + i * DD;
    const float* ei = emb + i * DD;
    #pragma unroll
    for (int d = 0; d < DD; d++)
        s += ai[d] * llw[p * DD + d] + ei[d] * lrw[p * DD + d];
    d_pref[i * PP + p] = s;
    float a = s * ew[p];
    float b = s * ew[PP + p];
    #pragma unroll
    for (int o = 16; o; o >>= 1) {
        a += __shfl_down_sync(0xffffffffu, a, o);
        b += __shfl_down_sync(0xffffffffu, b, o);
    }
    if (p == 0) { d_av[i] = a; d_bv[i] = b; }
}

// ---------------- combined value at (i,k) ----------------
__device__ __forceinline__ float comb_val(int i, int k, const float* __restrict__ dist,
                                          float eb, float wkf, float vhf) {
    if (k < PP) return d_pref[i * PP + k];
    if (k < PP + NN) {
        float e = d_av[i] + d_bv[k - PP] + eb;
        return (e >= 0.f) ? e : 0.01f * e;
    }
    if (k < PP + 2 * NN) return dist[(size_t)i * NN + (k - PP - NN)];
    if (k == PP + 2 * NN) return wkf;
    if (k == PP + 2 * NN + 1) return vhf;
    if (k == PP + 2 * NN + 2) return keep_bit(i) ? 1.f : 0.f;
    return 0.f;
}

// ---------------- A fill: fragment-offset iteration, coalesced uint4 stores ----
__global__ void k_fill_a(const float* __restrict__ dist, const float* __restrict__ edge_b,
                         const int* __restrict__ wk, const int* __restrict__ vh) {
    int kc = blockIdx.x, mt = blockIdx.y;
    int t = threadIdx.x;                 // 512
    int lane = t & 31, fragq = t >> 5;   // fragq 0..15
    int ki = fragq >> 3, mi = fragq & 7;
    int g = lane >> 2, tg = lane & 3;
    int i0 = mt * 128 + mi * 16 + g;
    int i1 = i0 + 8;
    int kA = kc * 32 + ki * 16 + tg * 2;
    int kB = kA + 8;
    float eb = edge_b[0], wkf = (float)wk[0], vhf = (float)vh[0];
    uint4 v;
    v.x = pack_bf16(comb_val(i0, kA, dist, eb, wkf, vhf), comb_val(i0, kA + 1, dist, eb, wkf, vhf));
    v.y = pack_bf16(comb_val(i1, kA, dist, eb, wkf, vhf), comb_val(i1, kA + 1, dist, eb, wkf, vhf));
    v.z = pack_bf16(comb_val(i0, kB, dist, eb, wkf, vhf), comb_val(i0, kB + 1, dist, eb, wkf, vhf));
    v.w = pack_bf16(comb_val(i1, kB, dist, eb, wkf, vhf), comb_val(i1, kB + 1, dist, eb, wkf, vhf));
    *(uint4*)(d_apack + (size_t)(mt * NCHUNK + kc) * TILE_U32 + fragq * 128 + lane * 4) = v;
}

// ---------------- B fill: fragment-offset iteration, coalesced uint2 stores ----
__global__ void k_fill_b(const float* __restrict__ combw) {
    int kc = blockIdx.x, nt = blockIdx.y;
    int t = threadIdx.x;                 // 1024
    int lane = t & 31, fragq = t >> 5;   // fragq 0..31
    int ki = fragq >> 4, ni = fragq & 15;
    int gb = lane >> 2, tg = lane & 3;
    int i = nt * 128 + ni * 8 + gb;      // weight row = output column
    int k0 = kc * 32 + ki * 16 + tg * 2;
    int k1 = k0 + 8;
    const float* wrow = combw + (size_t)i * KIN;
    float a0 = (k0     < KIN) ? wrow[k0]     : 0.f;
    float a1 = (k0 + 1 < KIN) ? wrow[k0 + 1] : 0.f;
    float b0 = (k1     < KIN) ? wrow[k1]     : 0.f;
    float b1 = (k1 + 1 < KIN) ? wrow[k1 + 1] : 0.f;
    uint2 v;
    v.x = pack_bf16(a0, a1);
    v.y = pack_bf16(b0, b1);
    *(uint2*)(d_bpack + (size_t)(nt * NCHUNK + kc) * TILE_U32 + fragq * 64 + lane * 2) = v;
}

// ---------------- stage loader: 16KB, 128 threads ----------------
__device__ __forceinline__ void load_stage(uint32_t sbase, int s,
                                           const uint32_t* aP, const uint32_t* bP, int tid) {
    uint32_t dst = sbase + s * STAGE_B + tid * 16;
    #pragma unroll
    for (int j = 0; j < 4; j++) CP_ASYNC16(dst + j * 2048, aP + tid * 4 + j * 512);
    dst += 8192;
    #pragma unroll
    for (int j = 0; j < 4; j++) CP_ASYNC16(dst + j * 2048, bP + tid * 4 + j * 512);
}

// ---------------- bf16 mma GEMM: C[128x128] per CTA, 4 warps 64x64 each --------
__global__ __launch_bounds__(128, 2) void k_gemm_mma(const float* __restrict__ bias,
                                                     float* __restrict__ C) {
    extern __shared__ __align__(16) uint32_t smu[];
    int tid = threadIdx.x, lane = tid & 31, wid = tid >> 5;
    int warpM = wid & 1, warpN = wid >> 1;      // 2 x 2 warps, 64x64 each
    int mt = blockIdx.y, nt = blockIdx.x;
    const uint32_t* aP0 = d_apack + (size_t)mt * NCHUNK * TILE_U32;
    const uint32_t* bP0 = d_bpack + (size_t)nt * NCHUNK * TILE_U32;
    uint32_t sbase = smem_u32(smu);

    float acc[4][8][4];
    #pragma unroll
    for (int m = 0; m < 4; m++)
        #pragma unroll
        for (int n = 0; n < 8; n++)
            #pragma unroll
            for (int q = 0; q < 4; q++) acc[m][n][q] = 0.f;

    #pragma unroll
    for (int p = 0; p < NSTG - 1; p++) {
        load_stage(sbase, p, aP0 + (size_t)p * TILE_U32, bP0 + (size_t)p * TILE_U32, tid);
        CP_COMMIT();
    }

    for (int kc = 0; kc < NCHUNK; kc++) {
        CP_WAIT(NSTG - 2);
        __syncthreads();
        int pf = kc + NSTG - 1;
        if (pf < NCHUNK)
            load_stage(sbase, pf % NSTG, aP0 + (size_t)pf * TILE_U32,
                       bP0 + (size_t)pf * TILE_U32, tid);
        CP_COMMIT();

        const uint32_t* As = smu + (kc % NSTG) * STAGE_U32;
        const uint32_t* Bs = As + TILE_U32;
        #pragma unroll
        for (int ki = 0; ki < 2; ki++) {
            uint32_t af[4][4];
            #pragma unroll
            for (int m = 0; m < 4; m++) {
                uint4 v = *(const uint4*)(As + ((ki * 8 + warpM * 4 + m) * 128 + lane * 4));
                af[m][0] = v.x; af[m][1] = v.y; af[m][2] = v.z; af[m][3] = v.w;
            }
            uint32_t bf[8][2];
            #pragma unroll
            for (int n = 0; n < 8; n++) {
                uint2 w = *(const uint2*)(Bs + ((ki * 16 + warpN * 8 + n) * 64 + lane * 2));
                bf[n][0] = w.x; bf[n][1] = w.y;
            }
            #pragma unroll
            for (int m = 0; m < 4; m++)
                #pragma unroll
                for (int n = 0; n < 8; n++) MMA16(acc[m][n], af[m], bf[n]);
        }
    }

    // epilogue
    int g = lane >> 2, tg = lane & 3;
    int rowBase = mt * BM + warpM * 64;
    int colBase = nt * BN + warpN * 64;
    #pragma unroll
    for (int m = 0; m < 4; m++) {
        int r0 = rowBase + m * 16 + g;
        #pragma unroll
        for (int n = 0; n < 8; n++) {
            int c = colBase + n * 8 + tg * 2;
            float2 bb = *(const float2*)(bias + c);
            float2 o0 = { acc[m][n][0] + bb.x, acc[m][n][1] + bb.y };
            float2 o1 = { acc[m][n][2] + bb.x, acc[m][n][3] + bb.y };
            *(float2*)(C + (size_t)r0 * NN + c) = o0;
            *(float2*)(C + (size_t)(r0 + 8) * NN + c) = o1;
        }
    }
}

// ---------------- register-resident row log-softmax ----------------
__global__ void k_lsm(float* __restrict__ out) {
    int i = blockIdx.x;
    int t = threadIdx.x;                 // 256
    int lane = t & 31, wid = t >> 5;
    float4* rp = (float4*)(out + (size_t)i * NN);
    float4 v0 = rp[t];
    float4 v1 = rp[t + 256];

    float m = fmaxf(fmaxf(fmaxf(v0.x, v0.y), fmaxf(v0.z, v0.w)),
                    fmaxf(fmaxf(v1.x, v1.y), fmaxf(v1.z, v1.w)));
    #pragma unroll
    for (int o = 16; o; o >>= 1) m = fmaxf(m, __shfl_xor_sync(0xffffffffu, m, o));
    __shared__ float sA[8];
    __shared__ float sbc;
    if (lane == 0) sA[wid] = m;
    __syncthreads();
    if (t == 0) {
        float mm = sA[0];
        #pragma unroll
        for (int w = 1; w < 8; w++) mm = fmaxf(mm, sA[w]);
        sbc = mm;
    }
    __syncthreads();
    float mx = sbc;

    float s = __expf(v0.x - mx) + __expf(v0.y - mx) + __expf(v0.z - mx) + __expf(v0.w - mx)
            + __expf(v1.x - mx) + __expf(v1.y - mx) + __expf(v1.z - mx) + __expf(v1.w - mx);
    #pragma unroll
    for (int o = 16; o; o >>= 1) s += __shfl_xor_sync(0xffffffffu, s, o);
    __syncthreads();
    if (lane == 0) sA[wid] = s;
    __syncthreads();
    if (t == 0) {
        float ss = 0.f;
        #pragma unroll
        for (int w = 0; w < 8; w++) ss += sA[w];
        sbc = logf(ss) + mx;
    }
    __syncthreads();
    float lse = sbc;

    v0.x -= lse; v0.y -= lse; v0.z -= lse; v0.w -= lse;
    v1.x -= lse; v1.y -= lse; v1.z -= lse; v1.w -= lse;
    rp[t] = v0;
    rp[t + 256] = v1;
}

// ---------------- launch ----------------
extern "C" void kernel_launch(void* const* d_in, const int* in_sizes, int n_in,
                              void* d_out, int out_size) {
    const float* dist   = (const float*)d_in[0];
    const float* emb    = (const float*)d_in[1];
    const float* llw    = (const float*)d_in[2];
    const float* llb    = (const float*)d_in[3];
    const float* lrw    = (const float*)d_in[4];
    const float* ew     = (const float*)d_in[5];
    const float* edge_b = (const float*)d_in[6];
    const float* combw  = (const float*)d_in[7];
    const float* combb  = (const float*)d_in[8];
    const int*   stops  = (const int*)d_in[9];
    const int*   wk     = (const int*)d_in[10];
    const int*   vh     = (const int*)d_in[11];
    float* out = (float*)d_out;

    k_init<<<NN, DD>>>(emb);
    k_scatter<<<(NSTOP + 255) / 256, 256>>>(stops);
    k_compact<<<NN, DD>>>(emb);
    k_aggv2<<<NSTOP, 256>>>();
    k_pref<<<NN / 8, 256>>>(emb, llw, llb, lrw, ew);

    dim3 fg(NCHUNK, 16);
    k_fill_a<<<fg, 512>>>(dist, edge_b, wk, vh);
    k_fill_b<<<fg, 1024>>>(combw);

    cudaFuncSetAttribute(k_gemm_mma, cudaFuncAttributeMaxDynamicSharedMemorySize, GEMM_SMEM);
    dim3 gg(NN / BN, NN / BM);
    k_gemm_mma<<<gg, 128, GEMM_SMEM>>>(combb, out);

    k_lsm<<<NN, 256>>>(out);
}